// round 13
// baseline (speedup 1.0000x reference)
#include <cuda_runtime.h>
#include <cuda_bf16.h>
#include <cuda_fp16.h>
#include <math.h>
#include <stdint.h>

// SoftEquivariantLayer v12: v11's two specialized kernels (byte-identical inner
// code) chunked into 4 pieces and software-pipelined across two streams:
// mixing(chunk c) overlaps scales(chunk c+1). Fork-join via events (capturable).

#define THREADS 256
#define NCHUNK  4
#define BLKS_PER_CHUNK 1024

// ---- kernel A SMEM ----
#define A_H1_B  0
#define A_W2_B  18432
#define A_W3_B  26624
#define A_W1_B  28672
#define A_B1_B  30720
#define A_B2_B  30976
#define A_SMEM  31232

// ---- kernel B SMEM ----
#define B_ZH_B  0
#define B_WH_B  34816
#define B_SC_B  67584
#define B_G_B   71680
#define B_SMEM  71744

__device__ __nv_bfloat16 gWpk[16384];
__device__ __half        gW2pk[4096];
__device__ float         gScales[4194304];

// ---------------- helpers ----------------
static __device__ __forceinline__ uint32_t s2u(const void* p) {
    uint32_t a;
    asm("{ .reg .u64 t; cvta.to.shared.u64 t, %1; cvt.u32.u64 %0, t; }" : "=r"(a) : "l"(p));
    return a;
}
static __device__ __forceinline__ float gelu_fast(float x) {
    float t = fabsf(x) * 0.7071067811865476f;
    float u = __fdividef(1.0f, fmaf(0.3275911f, t, 1.0f));
    float poly = u * fmaf(u, fmaf(u, fmaf(u, fmaf(u, 1.061405429f, -1.453152027f),
                                          1.421413741f), -0.284496736f), 0.254829592f);
    float e = __expf(-t * t);
    float erfv = fmaf(-poly, e, 1.0f);
    return x * 0.5f * (1.0f + copysignf(erfv, x));
}
static __device__ __forceinline__ float softplus_fast(float x) {
    float e = __expf(-fabsf(x));
    float l = __logf(1.0f + e);
    return x > 0.0f ? x + l : l;
}
static __device__ __forceinline__ void mma16bf(float4& d, uint32_t a0, uint32_t a1,
                                               uint32_t a2, uint32_t a3,
                                               uint32_t b0, uint32_t b1) {
    asm volatile("mma.sync.aligned.m16n8k16.row.col.f32.bf16.bf16.f32 "
                 "{%0,%1,%2,%3}, {%4,%5,%6,%7}, {%8,%9}, {%0,%1,%2,%3};"
                 : "+f"(d.x), "+f"(d.y), "+f"(d.z), "+f"(d.w)
                 : "r"(a0), "r"(a1), "r"(a2), "r"(a3), "r"(b0), "r"(b1));
}
static __device__ __forceinline__ void mma16h(float4& d, uint32_t a0, uint32_t a1,
                                              uint32_t a2, uint32_t a3,
                                              uint32_t b0, uint32_t b1) {
    asm volatile("mma.sync.aligned.m16n8k16.row.col.f32.f16.f16.f32 "
                 "{%0,%1,%2,%3}, {%4,%5,%6,%7}, {%8,%9}, {%0,%1,%2,%3};"
                 : "+f"(d.x), "+f"(d.y), "+f"(d.z), "+f"(d.w)
                 : "r"(a0), "r"(a1), "r"(a2), "r"(a3), "r"(b0), "r"(b1));
}
static __device__ __forceinline__ void ldsm4(uint32_t& r0, uint32_t& r1,
                                             uint32_t& r2, uint32_t& r3, uint32_t addr) {
    asm volatile("ldmatrix.sync.aligned.m8n8.x4.shared.b16 {%0,%1,%2,%3}, [%4];"
                 : "=r"(r0), "=r"(r1), "=r"(r2), "=r"(r3) : "r"(addr));
}

// ---------------- prep kernels (validated layouts) ----------------
__global__ void prep_kernel(const float* __restrict__ mixw) {
    int g = blockIdx.x * 256 + threadIdx.x;
    int i = g >> 11, j = (g >> 8) & 7, k = (g >> 4) & 15, d = g & 15;
    int n  = i * 16 + k;
    int kd = j * 16 + d;
    int nh = n >> 6, nt = (n >> 3) & 7, qt = n & 7;
    int ks = kd >> 4, kr = kd & 15;
    int b  = kr >> 3, qc = (kr & 7) >> 1, h = kr & 1;
    int lid = qt * 4 + qc;
    int idx = nh * 8192 + ks * 1024 + (nt >> 1) * 256 + lid * 8 + (nt & 1) * 4 + b * 2 + h;
    gWpk[idx] = __float2bfloat16(mixw[g]);
}
__global__ void prep2_kernel(const float* __restrict__ w2) {
    int g = blockIdx.x * 256 + threadIdx.x;
    int o = g >> 6;
    int i = g & 63;
    int nt = o >> 3, qt = o & 7;
    int ks = i >> 4, kr = i & 15;
    int b  = kr >> 3, qc = (kr & 7) >> 1, h = kr & 1;
    int lid = qt * 4 + qc;
    int idx = ks * 1024 + (nt >> 1) * 256 + lid * 8 + (nt & 1) * 4 + b * 2 + h;
    gW2pk[idx] = __float2half_rn(w2[g]);
}

// ================= kernel A: norms + gating MLP -> gScales =================
__global__ void __launch_bounds__(THREADS, 2)
scales_kernel(const float* __restrict__ z,
              const float* __restrict__ w1,
              const float* __restrict__ b1,
              const float* __restrict__ b2,
              const float* __restrict__ w3,
              int blk0)
{
    extern __shared__ char smem[];
    float* w1s = (float*)(smem + A_W1_B);
    float* w3t = (float*)(smem + A_W3_B);
    float* b1s = (float*)(smem + A_B1_B);
    float* b2s = (float*)(smem + A_B2_B);

    const int tid = threadIdx.x;
    const int wid = tid >> 5;
    const int lid = tid & 31;
    const int row0 = (blockIdx.x + blk0) * 128;
    const uint32_t smb = s2u(smem);

    #pragma unroll
    for (int e = 0; e < 2; ++e) {
        int i = e * 256 + tid;
        w1s[i] = w1[i];
        int j = i >> 6, col = i & 63;
        w3t[col * 8 + j] = w3[i];
        ((float4*)(smem + A_W2_B))[i] = ((const float4*)gW2pk)[i];
    }
    if (tid < 64) { b1s[tid] = b1[tid]; b2s[tid] = b2[tid]; }
    __syncthreads();

    const int r0 = wid * 16;
    const int lrow = lid >> 1;
    const int half = lid & 1;
    const int row = r0 + lrow;

    float pn[8];
    #pragma unroll
    for (int j = 0; j < 8; ++j) pn[j] = 0.0f;
    {
        const float4* zg4 = (const float4*)z;
        size_t base = (size_t)(row0 + row) * 32;
        #pragma unroll
        for (int cc = 0; cc < 2; ++cc) {
            #pragma unroll
            for (int j = 0; j < 8; ++j) {
                float4 v = zg4[base + j * 4 + 2 * half + cc];
                pn[j] += v.x * v.x + v.y * v.y + v.z * v.z + v.w * v.w;
            }
        }
    }
    float nrm[8];
    #pragma unroll
    for (int j = 0; j < 8; ++j) {
        float o = __shfl_xor_sync(0xffffffffu, pn[j], 1);
        nrm[j] = sqrtf(pn[j] + o) + 1e-8f;
    }

    {
        char* hrow = smem + A_H1_B + row * 144 + half * 64;
        #pragma unroll
        for (int q = 0; q < 4; ++q) {
            uint32_t pk[4];
            #pragma unroll
            for (int s = 0; s < 4; ++s) {
                int o = half * 32 + q * 8 + 2 * s;
                const float4* wr = (const float4*)(w1s + o * 8);
                float4 wa = wr[0], wb = wr[1];
                float a0 = b1s[o];
                a0 += nrm[0] * wa.x + nrm[1] * wa.y + nrm[2] * wa.z + nrm[3] * wa.w;
                a0 += nrm[4] * wb.x + nrm[5] * wb.y + nrm[6] * wb.z + nrm[7] * wb.w;
                const float4* wr2 = (const float4*)(w1s + (o + 1) * 8);
                float4 wc = wr2[0], wd = wr2[1];
                float a1 = b1s[o + 1];
                a1 += nrm[0] * wc.x + nrm[1] * wc.y + nrm[2] * wc.z + nrm[3] * wc.w;
                a1 += nrm[4] * wd.x + nrm[5] * wd.y + nrm[6] * wd.z + nrm[7] * wd.w;
                __half2 hh = __floats2half2_rn(gelu_fast(a0), gelu_fast(a1));
                pk[s] = *(uint32_t*)&hh;
            }
            *(uint4*)(hrow + q * 16) = make_uint4(pk[0], pk[1], pk[2], pk[3]);
        }
    }
    __syncwarp();

    const int qt = lid >> 2;
    const int qc = lid & 3;
    float4 acc[8];
    #pragma unroll
    for (int nt = 0; nt < 8; ++nt) acc[nt] = make_float4(0.f, 0.f, 0.f, 0.f);
    {
        const int lm_row = ((lid >> 3) & 1) * 8 + (lid & 7);
        const int lm_col = (lid >> 4) * 16;
        const uint32_t abase = smb + A_H1_B + (r0 + lm_row) * 144 + lm_col;
        const char* wbase = smem + A_W2_B;
        #pragma unroll
        for (int ks = 0; ks < 4; ++ks) {
            uint32_t a0, a1, a2, a3;
            ldsm4(a0, a1, a2, a3, abase + ks * 32);
            const char* wp = wbase + ks * 2048 + lid * 16;
            uint4 l0 = *(const uint4*)(wp);
            uint4 l1 = *(const uint4*)(wp + 512);
            uint4 l2 = *(const uint4*)(wp + 1024);
            uint4 l3 = *(const uint4*)(wp + 1536);
            mma16h(acc[0], a0, a1, a2, a3, l0.x, l0.y);
            mma16h(acc[1], a0, a1, a2, a3, l0.z, l0.w);
            mma16h(acc[2], a0, a1, a2, a3, l1.x, l1.y);
            mma16h(acc[3], a0, a1, a2, a3, l1.z, l1.w);
            mma16h(acc[4], a0, a1, a2, a3, l2.x, l2.y);
            mma16h(acc[5], a0, a1, a2, a3, l2.z, l2.w);
            mma16h(acc[6], a0, a1, a2, a3, l3.x, l3.y);
            mma16h(acc[7], a0, a1, a2, a3, l3.z, l3.w);
        }
    }

    float s0[8], s1[8];
    #pragma unroll
    for (int j = 0; j < 8; ++j) { s0[j] = 0.0f; s1[j] = 0.0f; }
    #pragma unroll
    for (int nt = 0; nt < 8; ++nt) {
        int c0 = nt * 8 + 2 * qc;
        float bb0 = b2s[c0], bb1 = b2s[c0 + 1];
        float h00 = gelu_fast(acc[nt].x + bb0);
        float h01 = gelu_fast(acc[nt].y + bb1);
        float h10 = gelu_fast(acc[nt].z + bb0);
        float h11 = gelu_fast(acc[nt].w + bb1);
        const float4* wa = (const float4*)(w3t + c0 * 8);
        const float4* wb = (const float4*)(w3t + (c0 + 1) * 8);
        float4 wa0 = wa[0], wa1 = wa[1], wb0 = wb[0], wb1 = wb[1];
        s0[0] += h00 * wa0.x + h01 * wb0.x;  s0[1] += h00 * wa0.y + h01 * wb0.y;
        s0[2] += h00 * wa0.z + h01 * wb0.z;  s0[3] += h00 * wa0.w + h01 * wb0.w;
        s0[4] += h00 * wa1.x + h01 * wb1.x;  s0[5] += h00 * wa1.y + h01 * wb1.y;
        s0[6] += h00 * wa1.z + h01 * wb1.z;  s0[7] += h00 * wa1.w + h01 * wb1.w;
        s1[0] += h10 * wa0.x + h11 * wb0.x;  s1[1] += h10 * wa0.y + h11 * wb0.y;
        s1[2] += h10 * wa0.z + h11 * wb0.z;  s1[3] += h10 * wa0.w + h11 * wb0.w;
        s1[4] += h10 * wa1.x + h11 * wb1.x;  s1[5] += h10 * wa1.y + h11 * wb1.y;
        s1[6] += h10 * wa1.z + h11 * wb1.z;  s1[7] += h10 * wa1.w + h11 * wb1.w;
    }
    #pragma unroll
    for (int j = 0; j < 8; ++j) {
        s0[j] += __shfl_xor_sync(0xffffffffu, s0[j], 1);
        s0[j] += __shfl_xor_sync(0xffffffffu, s0[j], 2);
        s1[j] += __shfl_xor_sync(0xffffffffu, s1[j], 1);
        s1[j] += __shfl_xor_sync(0xffffffffu, s1[j], 2);
    }
    if (qc == 0) {
        float* d0 = gScales + (size_t)(row0 + r0 + qt) * 8;
        float* d1 = gScales + (size_t)(row0 + r0 + qt + 8) * 8;
        *(float4*)(d0)     = make_float4(softplus_fast(s0[0]), softplus_fast(s0[1]),
                                         softplus_fast(s0[2]), softplus_fast(s0[3]));
        *(float4*)(d0 + 4) = make_float4(softplus_fast(s0[4]), softplus_fast(s0[5]),
                                         softplus_fast(s0[6]), softplus_fast(s0[7]));
        *(float4*)(d1)     = make_float4(softplus_fast(s1[0]), softplus_fast(s1[1]),
                                         softplus_fast(s1[2]), softplus_fast(s1[3]));
        *(float4*)(d1 + 4) = make_float4(softplus_fast(s1[4]), softplus_fast(s1[5]),
                                         softplus_fast(s1[6]), softplus_fast(s1[7]));
    }
}

// ================= kernel B: mixing GEMM + epilogue =================
__global__ void __launch_bounds__(THREADS, 2)
mixing_kernel(const float* __restrict__ z,
              const float* __restrict__ gb,
              float* __restrict__ out,
              int blk0)
{
    extern __shared__ char smem[];
    float* scs = (float*)(smem + B_SC_B);
    float* gts = (float*)(smem + B_G_B);

    const int tid = threadIdx.x;
    const int wid = tid >> 5;
    const int lid = tid & 31;
    const int blk = blockIdx.x + blk0;
    const int row0 = blk * 128;
    const uint32_t smb = s2u(smem);

    {
        const float4* s = (const float4*)gWpk;
        float4* d4 = (float4*)(smem + B_WH_B);
        #pragma unroll
        for (int e = 0; e < 8; ++e) d4[e * 256 + tid] = s[e * 256 + tid];
    }
    ((float4*)scs)[tid] = ((const float4*)gScales)[blk * 256 + tid];
    if (tid < 8) gts[tid] = 1.0f / (1.0f + __expf(-gb[tid]));
    {
        const float4* zg = (const float4*)(z + (size_t)row0 * 128);
        #pragma unroll
        for (int e = 0; e < 16; ++e) {
            int idx = e * 256 + tid;
            int row = idx >> 5;
            int c4  = idx & 31;
            float4 v = zg[idx];
            __nv_bfloat162 p0 = __floats2bfloat162_rn(v.x, v.y);
            __nv_bfloat162 p1 = __floats2bfloat162_rn(v.z, v.w);
            uint2 pr = make_uint2(*(uint32_t*)&p0, *(uint32_t*)&p1);
            *(uint2*)(smem + B_ZH_B + row * 272 + c4 * 8) = pr;
        }
    }
    __syncthreads();

    const int mw = wid & 3;
    const int nh = wid >> 2;

    float4 acc[8], acc2[8];
    #pragma unroll
    for (int nt = 0; nt < 8; ++nt) {
        acc[nt]  = make_float4(0.f, 0.f, 0.f, 0.f);
        acc2[nt] = make_float4(0.f, 0.f, 0.f, 0.f);
    }

    const int lm_row = ((lid >> 3) & 1) * 8 + (lid & 7);
    const int lm_col = (lid >> 4) * 16;
    const uint32_t abase = smb + B_ZH_B + (mw * 32 + lm_row) * 272 + lm_col;
    const char* wbase = smem + B_WH_B + nh * 16384;

    #pragma unroll
    for (int ks = 0; ks < 8; ++ks) {
        uint32_t a0, a1, a2, a3, c0, c1, c2, c3;
        ldsm4(a0, a1, a2, a3, abase + ks * 32);
        ldsm4(c0, c1, c2, c3, abase + 16 * 272 + ks * 32);
        const char* wp = wbase + ks * 2048 + lid * 16;
        uint4 l0 = *(const uint4*)(wp);
        uint4 l1 = *(const uint4*)(wp + 512);
        uint4 l2 = *(const uint4*)(wp + 1024);
        uint4 l3 = *(const uint4*)(wp + 1536);
        mma16bf(acc[0], a0, a1, a2, a3, l0.x, l0.y);
        mma16bf(acc[1], a0, a1, a2, a3, l0.z, l0.w);
        mma16bf(acc[2], a0, a1, a2, a3, l1.x, l1.y);
        mma16bf(acc[3], a0, a1, a2, a3, l1.z, l1.w);
        mma16bf(acc[4], a0, a1, a2, a3, l2.x, l2.y);
        mma16bf(acc[5], a0, a1, a2, a3, l2.z, l2.w);
        mma16bf(acc[6], a0, a1, a2, a3, l3.x, l3.y);
        mma16bf(acc[7], a0, a1, a2, a3, l3.z, l3.w);
        mma16bf(acc2[0], c0, c1, c2, c3, l0.x, l0.y);
        mma16bf(acc2[1], c0, c1, c2, c3, l0.z, l0.w);
        mma16bf(acc2[2], c0, c1, c2, c3, l1.x, l1.y);
        mma16bf(acc2[3], c0, c1, c2, c3, l1.z, l1.w);
        mma16bf(acc2[4], c0, c1, c2, c3, l2.x, l2.y);
        mma16bf(acc2[5], c0, c1, c2, c3, l2.z, l2.w);
        mma16bf(acc2[6], c0, c1, c2, c3, l3.x, l3.y);
        mma16bf(acc2[7], c0, c1, c2, c3, l3.z, l3.w);
    }

    const int qt = lid >> 2;
    const int qc = lid & 3;
    #pragma unroll
    for (int nt = 0; nt < 8; ++nt) {
        const int bundle = nh * 4 + (nt >> 1);
        const float g = gts[bundle];
        const int x0 = nh * 64 + nt * 8 + 2 * qc;
        #pragma unroll
        for (int mt = 0; mt < 2; ++mt) {
            float4 a = (mt == 0) ? acc[nt] : acc2[nt];
            #pragma unroll
            for (int rh = 0; rh < 2; ++rh) {
                const int r = mw * 32 + mt * 16 + rh * 8 + qt;
                const float s1 = 1.0f + scs[r * 8 + bundle];
                float2 zv = *(const float2*)(z + (size_t)(row0 + r) * 128 + x0);
                float m0 = (rh == 0) ? a.x : a.z;
                float m1 = (rh == 0) ? a.y : a.w;
                float2 o = make_float2(zv.x * s1 + g * m0, zv.y * s1 + g * m1);
                *(float2*)(out + (size_t)(row0 + r) * 128 + x0) = o;
            }
        }
    }
}

extern "C" void kernel_launch(void* const* d_in, const int* in_sizes, int n_in,
                              void* d_out, int out_size)
{
    const float* z    = (const float*)d_in[0];
    const float* w1   = (const float*)d_in[1];
    const float* b1   = (const float*)d_in[2];
    const float* w2   = (const float*)d_in[3];
    const float* b2   = (const float*)d_in[4];
    const float* w3   = (const float*)d_in[5];
    const float* mixw = (const float*)d_in[6];
    const float* gb   = (const float*)d_in[7];
    float* out = (float*)d_out;

    static cudaStream_t sA = nullptr, sB = nullptr;
    static cudaEvent_t evFork, evA[NCHUNK], evJoin;
    static bool init_done = false;
    if (!init_done) {
        cudaStreamCreateWithFlags(&sA, cudaStreamNonBlocking);
        cudaStreamCreateWithFlags(&sB, cudaStreamNonBlocking);
        cudaEventCreateWithFlags(&evFork, cudaEventDisableTiming);
        cudaEventCreateWithFlags(&evJoin, cudaEventDisableTiming);
        for (int c = 0; c < NCHUNK; ++c)
            cudaEventCreateWithFlags(&evA[c], cudaEventDisableTiming);
        cudaFuncSetAttribute(mixing_kernel,
                             cudaFuncAttributeMaxDynamicSharedMemorySize, B_SMEM);
        init_done = true;
    }

    // prep on the captured (default) stream, then fork.
    prep_kernel<<<64, 256>>>(mixw);
    prep2_kernel<<<16, 256>>>(w2);
    cudaEventRecord(evFork, 0);
    cudaStreamWaitEvent(sA, evFork, 0);
    cudaStreamWaitEvent(sB, evFork, 0);

    for (int c = 0; c < NCHUNK; ++c) {
        int blk0 = c * BLKS_PER_CHUNK;
        scales_kernel<<<BLKS_PER_CHUNK, THREADS, A_SMEM, sA>>>(z, w1, b1, b2, w3, blk0);
        cudaEventRecord(evA[c], sA);
        cudaStreamWaitEvent(sB, evA[c], 0);
        mixing_kernel<<<BLKS_PER_CHUNK, THREADS, B_SMEM, sB>>>(z, gb, out, blk0);
    }
    cudaEventRecord(evJoin, sB);
    cudaStreamWaitEvent(0, evJoin, 0);   // join back to the captured stream
}

// round 14
// speedup vs baseline: 1.0876x; 1.0876x over previous
#include <cuda_runtime.h>
#include <cuda_bf16.h>
#include <cuda_fp16.h>
#include <math.h>
#include <stdint.h>

// SoftEquivariantLayer v13: sequential two-kernel design, both persistent (4
// row-tiles per CTA, grid 1024). Scales kernel's layer-1 moved to tf32
// m16n8k8 mma (fragment-packed w1). Mixing kernel = v11 inner code + tile loop.

#define THREADS 256
#define TILES   4

// ---- scales kernel SMEM ----
#define A_H1_B   0          // h1 fp16 [128] rows, 144B stride (18432)
#define A_NRM_B  18432      // norms f32 [128][9] (4608)
#define A_W2_B   23040      // packed w2 frags fp16 (8192)
#define A_W1PK_B 31232      // packed w1 frags f32 (2048)
#define A_W3_B   33280      // w3^T [64][8] f32 (2048)
#define A_B1_B   35328      // 256
#define A_B2_B   35584      // 256
#define A_SMEM   35840

// ---- mixing kernel SMEM ----
#define B_ZH_B  0           // Z bf16 [128] rows, 272B stride (34816)
#define B_WH_B  34816       // packed mixing B frags bf16 (32768)
#define B_SC_B  67584       // scales [128][8] f32 (4096)
#define B_G_B   71680       // 64
#define B_SMEM  71744

__device__ __nv_bfloat16 gWpk[16384];     // mix_w bf16 fragment-packed
__device__ __half        gW2pk[4096];     // w2 fp16 fragment-packed
__device__ float         gW1pk[512];      // w1 f32 fragment-packed (m16n8k8)
__device__ float         gScales[4194304];

// ---------------- helpers ----------------
static __device__ __forceinline__ uint32_t s2u(const void* p) {
    uint32_t a;
    asm("{ .reg .u64 t; cvta.to.shared.u64 t, %1; cvt.u32.u64 %0, t; }" : "=r"(a) : "l"(p));
    return a;
}
static __device__ __forceinline__ float gelu_fast(float x) {
    float t = fabsf(x) * 0.7071067811865476f;
    float u = __fdividef(1.0f, fmaf(0.3275911f, t, 1.0f));
    float poly = u * fmaf(u, fmaf(u, fmaf(u, fmaf(u, 1.061405429f, -1.453152027f),
                                          1.421413741f), -0.284496736f), 0.254829592f);
    float e = __expf(-t * t);
    float erfv = fmaf(-poly, e, 1.0f);
    return x * 0.5f * (1.0f + copysignf(erfv, x));
}
static __device__ __forceinline__ float softplus_fast(float x) {
    float e = __expf(-fabsf(x));
    float l = __logf(1.0f + e);
    return x > 0.0f ? x + l : l;
}
static __device__ __forceinline__ void mma16bf(float4& d, uint32_t a0, uint32_t a1,
                                               uint32_t a2, uint32_t a3,
                                               uint32_t b0, uint32_t b1) {
    asm volatile("mma.sync.aligned.m16n8k16.row.col.f32.bf16.bf16.f32 "
                 "{%0,%1,%2,%3}, {%4,%5,%6,%7}, {%8,%9}, {%0,%1,%2,%3};"
                 : "+f"(d.x), "+f"(d.y), "+f"(d.z), "+f"(d.w)
                 : "r"(a0), "r"(a1), "r"(a2), "r"(a3), "r"(b0), "r"(b1));
}
static __device__ __forceinline__ void mma16h(float4& d, uint32_t a0, uint32_t a1,
                                              uint32_t a2, uint32_t a3,
                                              uint32_t b0, uint32_t b1) {
    asm volatile("mma.sync.aligned.m16n8k16.row.col.f32.f16.f16.f32 "
                 "{%0,%1,%2,%3}, {%4,%5,%6,%7}, {%8,%9}, {%0,%1,%2,%3};"
                 : "+f"(d.x), "+f"(d.y), "+f"(d.z), "+f"(d.w)
                 : "r"(a0), "r"(a1), "r"(a2), "r"(a3), "r"(b0), "r"(b1));
}
static __device__ __forceinline__ void mma8tf(float4& d, uint32_t a0, uint32_t a1,
                                              uint32_t a2, uint32_t a3,
                                              uint32_t b0, uint32_t b1) {
    asm volatile("mma.sync.aligned.m16n8k8.row.col.f32.tf32.tf32.f32 "
                 "{%0,%1,%2,%3}, {%4,%5,%6,%7}, {%8,%9}, {%0,%1,%2,%3};"
                 : "+f"(d.x), "+f"(d.y), "+f"(d.z), "+f"(d.w)
                 : "r"(a0), "r"(a1), "r"(a2), "r"(a3), "r"(b0), "r"(b1));
}
static __device__ __forceinline__ void ldsm4(uint32_t& r0, uint32_t& r1,
                                             uint32_t& r2, uint32_t& r3, uint32_t addr) {
    asm volatile("ldmatrix.sync.aligned.m8n8.x4.shared.b16 {%0,%1,%2,%3}, [%4];"
                 : "=r"(r0), "=r"(r1), "=r"(r2), "=r"(r3) : "r"(addr));
}

// ---------------- prep kernels ----------------
__global__ void prep_kernel(const float* __restrict__ mixw) {
    int g = blockIdx.x * 256 + threadIdx.x;
    int i = g >> 11, j = (g >> 8) & 7, k = (g >> 4) & 15, d = g & 15;
    int n  = i * 16 + k;
    int kd = j * 16 + d;
    int nh = n >> 6, nt = (n >> 3) & 7, qt = n & 7;
    int ks = kd >> 4, kr = kd & 15;
    int b  = kr >> 3, qc = (kr & 7) >> 1, h = kr & 1;
    int lid = qt * 4 + qc;
    int idx = nh * 8192 + ks * 1024 + (nt >> 1) * 256 + lid * 8 + (nt & 1) * 4 + b * 2 + h;
    gWpk[idx] = __float2bfloat16(mixw[g]);
}
__global__ void prep2_kernel(const float* __restrict__ w2) {
    int g = blockIdx.x * 256 + threadIdx.x;
    int o = g >> 6;
    int i = g & 63;
    int nt = o >> 3, qt = o & 7;
    int ks = i >> 4, kr = i & 15;
    int b  = kr >> 3, qc = (kr & 7) >> 1, h = kr & 1;
    int lid = qt * 4 + qc;
    int idx = ks * 1024 + (nt >> 1) * 256 + lid * 8 + (nt & 1) * 4 + b * 2 + h;
    gW2pk[idx] = __float2half_rn(w2[g]);
}
// w1[64][8] -> per-lane frags for m16n8k8 tf32 (B col = qt, k = qc / qc+4)
__global__ void prep3_kernel(const float* __restrict__ w1) {
    int g = threadIdx.x + blockIdx.x * 256;      // 512
    int o = g >> 3, k = g & 7;
    int nt = o >> 3, qt = o & 7;
    int qc = k & 3, h = k >> 2;
    int idx = (nt >> 1) * 128 + (qt * 4 + qc) * 4 + (nt & 1) * 2 + h;
    gW1pk[idx] = w1[g];
}

// ================= kernel A: norms + gating MLP -> gScales =================
__global__ void __launch_bounds__(THREADS, 2)
scales_kernel(const float* __restrict__ z,
              const float* __restrict__ b1,
              const float* __restrict__ b2,
              const float* __restrict__ w3)
{
    extern __shared__ char smem[];
    float* nrs = (float*)(smem + A_NRM_B);
    float* w3t = (float*)(smem + A_W3_B);
    float* b1s = (float*)(smem + A_B1_B);
    float* b2s = (float*)(smem + A_B2_B);

    const int tid = threadIdx.x;
    const int wid = tid >> 5;
    const int lid = tid & 31;
    const uint32_t smb = s2u(smem);

    // ---- one-time staging ----
    #pragma unroll
    for (int e = 0; e < 2; ++e) {
        int i = e * 256 + tid;
        int j = i >> 6, col = i & 63;
        w3t[col * 8 + j] = w3[i];
        ((float4*)(smem + A_W2_B))[i] = ((const float4*)gW2pk)[i];
    }
    if (tid < 128) ((float4*)(smem + A_W1PK_B))[tid] = ((const float4*)gW1pk)[tid];
    if (tid < 64) { b1s[tid] = b1[tid]; b2s[tid] = b2[tid]; }
    __syncthreads();

    const int r0 = wid * 16;
    const int lrow = lid >> 1;
    const int half = lid & 1;
    const int qt = lid >> 2;
    const int qc = lid & 3;

    for (int t = 0; t < TILES; ++t) {
        const int row0 = (blockIdx.x * TILES + t) * 128;

        // ---- norms from global z; store to nrs [128][9] ----
        float pn[8];
        #pragma unroll
        for (int j = 0; j < 8; ++j) pn[j] = 0.0f;
        {
            const float4* zg4 = (const float4*)z;
            size_t base = (size_t)(row0 + r0 + lrow) * 32;
            #pragma unroll
            for (int cc = 0; cc < 2; ++cc) {
                #pragma unroll
                for (int j = 0; j < 8; ++j) {
                    float4 v = zg4[base + j * 4 + 2 * half + cc];
                    pn[j] += v.x * v.x + v.y * v.y + v.z * v.z + v.w * v.w;
                }
            }
        }
        __syncwarp();    // prev-tile A-frag reads done before overwrite
        #pragma unroll
        for (int j = 0; j < 8; ++j) {
            float o = __shfl_xor_sync(0xffffffffu, pn[j], 1);
            pn[j] = sqrtf(pn[j] + o) + 1e-8f;
        }
        if (half == 0) {
            float* nr = nrs + (r0 + lrow) * 9;
            #pragma unroll
            for (int j = 0; j < 8; ++j) nr[j] = pn[j];
        }
        __syncwarp();

        // ---- layer 1: tf32 m16n8k8 mma (A = norms, B = packed w1) ----
        float4 hacc[8];
        {
            uint32_t a0 = __float_as_uint(nrs[(r0 + qt) * 9 + qc]);
            uint32_t a1 = __float_as_uint(nrs[(r0 + qt + 8) * 9 + qc]);
            uint32_t a2 = __float_as_uint(nrs[(r0 + qt) * 9 + qc + 4]);
            uint32_t a3 = __float_as_uint(nrs[(r0 + qt + 8) * 9 + qc + 4]);
            const uint4* w1p = (const uint4*)(smem + A_W1PK_B);
            #pragma unroll
            for (int g = 0; g < 4; ++g) {
                uint4 wq = w1p[g * 32 + lid];
                hacc[2 * g]     = make_float4(0.f, 0.f, 0.f, 0.f);
                hacc[2 * g + 1] = make_float4(0.f, 0.f, 0.f, 0.f);
                mma8tf(hacc[2 * g],     a0, a1, a2, a3, wq.x, wq.y);
                mma8tf(hacc[2 * g + 1], a0, a1, a2, a3, wq.z, wq.w);
            }
        }
        // bias + gelu -> h1 fp16 tile
        {
            #pragma unroll
            for (int nt = 0; nt < 8; ++nt) {
                int c0 = nt * 8 + 2 * qc;
                float2 bb = *(const float2*)(b1s + c0);
                float h00 = gelu_fast(hacc[nt].x + bb.x);
                float h01 = gelu_fast(hacc[nt].y + bb.y);
                float h10 = gelu_fast(hacc[nt].z + bb.x);
                float h11 = gelu_fast(hacc[nt].w + bb.y);
                __half2 p0 = __floats2half2_rn(h00, h01);
                __half2 p1 = __floats2half2_rn(h10, h11);
                *(__half2*)(smem + A_H1_B + (r0 + qt) * 144 + c0 * 2)     = p0;
                *(__half2*)(smem + A_H1_B + (r0 + qt + 8) * 144 + c0 * 2) = p1;
            }
        }
        __syncwarp();

        // ---- layer 2: fp16 m16n8k16 (v11 verbatim) ----
        float4 acc[8];
        #pragma unroll
        for (int nt = 0; nt < 8; ++nt) acc[nt] = make_float4(0.f, 0.f, 0.f, 0.f);
        {
            const int lm_row = ((lid >> 3) & 1) * 8 + (lid & 7);
            const int lm_col = (lid >> 4) * 16;
            const uint32_t abase = smb + A_H1_B + (r0 + lm_row) * 144 + lm_col;
            const char* wbase = smem + A_W2_B;
            #pragma unroll
            for (int ks = 0; ks < 4; ++ks) {
                uint32_t a0, a1, a2, a3;
                ldsm4(a0, a1, a2, a3, abase + ks * 32);
                const char* wp = wbase + ks * 2048 + lid * 16;
                uint4 l0 = *(const uint4*)(wp);
                uint4 l1 = *(const uint4*)(wp + 512);
                uint4 l2 = *(const uint4*)(wp + 1024);
                uint4 l3 = *(const uint4*)(wp + 1536);
                mma16h(acc[0], a0, a1, a2, a3, l0.x, l0.y);
                mma16h(acc[1], a0, a1, a2, a3, l0.z, l0.w);
                mma16h(acc[2], a0, a1, a2, a3, l1.x, l1.y);
                mma16h(acc[3], a0, a1, a2, a3, l1.z, l1.w);
                mma16h(acc[4], a0, a1, a2, a3, l2.x, l2.y);
                mma16h(acc[5], a0, a1, a2, a3, l2.z, l2.w);
                mma16h(acc[6], a0, a1, a2, a3, l3.x, l3.y);
                mma16h(acc[7], a0, a1, a2, a3, l3.z, l3.w);
            }
        }

        // ---- bias + gelu; layer-3 partials; quad reduce; softplus ----
        float s0[8], s1[8];
        #pragma unroll
        for (int j = 0; j < 8; ++j) { s0[j] = 0.0f; s1[j] = 0.0f; }
        #pragma unroll
        for (int nt = 0; nt < 8; ++nt) {
            int c0 = nt * 8 + 2 * qc;
            float bb0 = b2s[c0], bb1 = b2s[c0 + 1];
            float h00 = gelu_fast(acc[nt].x + bb0);
            float h01 = gelu_fast(acc[nt].y + bb1);
            float h10 = gelu_fast(acc[nt].z + bb0);
            float h11 = gelu_fast(acc[nt].w + bb1);
            const float4* wa = (const float4*)(w3t + c0 * 8);
            const float4* wb = (const float4*)(w3t + (c0 + 1) * 8);
            float4 wa0 = wa[0], wa1 = wa[1], wb0 = wb[0], wb1 = wb[1];
            s0[0] += h00 * wa0.x + h01 * wb0.x;  s0[1] += h00 * wa0.y + h01 * wb0.y;
            s0[2] += h00 * wa0.z + h01 * wb0.z;  s0[3] += h00 * wa0.w + h01 * wb0.w;
            s0[4] += h00 * wa1.x + h01 * wb1.x;  s0[5] += h00 * wa1.y + h01 * wb1.y;
            s0[6] += h00 * wa1.z + h01 * wb1.z;  s0[7] += h00 * wa1.w + h01 * wb1.w;
            s1[0] += h10 * wa0.x + h11 * wb0.x;  s1[1] += h10 * wa0.y + h11 * wb0.y;
            s1[2] += h10 * wa0.z + h11 * wb0.z;  s1[3] += h10 * wa0.w + h11 * wb0.w;
            s1[4] += h10 * wa1.x + h11 * wb1.x;  s1[5] += h10 * wa1.y + h11 * wb1.y;
            s1[6] += h10 * wa1.z + h11 * wb1.z;  s1[7] += h10 * wa1.w + h11 * wb1.w;
        }
        #pragma unroll
        for (int j = 0; j < 8; ++j) {
            s0[j] += __shfl_xor_sync(0xffffffffu, s0[j], 1);
            s0[j] += __shfl_xor_sync(0xffffffffu, s0[j], 2);
            s1[j] += __shfl_xor_sync(0xffffffffu, s1[j], 1);
            s1[j] += __shfl_xor_sync(0xffffffffu, s1[j], 2);
        }
        if (qc == 0) {
            float* d0 = gScales + (size_t)(row0 + r0 + qt) * 8;
            float* d1 = gScales + (size_t)(row0 + r0 + qt + 8) * 8;
            *(float4*)(d0)     = make_float4(softplus_fast(s0[0]), softplus_fast(s0[1]),
                                             softplus_fast(s0[2]), softplus_fast(s0[3]));
            *(float4*)(d0 + 4) = make_float4(softplus_fast(s0[4]), softplus_fast(s0[5]),
                                             softplus_fast(s0[6]), softplus_fast(s0[7]));
            *(float4*)(d1)     = make_float4(softplus_fast(s1[0]), softplus_fast(s1[1]),
                                             softplus_fast(s1[2]), softplus_fast(s1[3]));
            *(float4*)(d1 + 4) = make_float4(softplus_fast(s1[4]), softplus_fast(s1[5]),
                                             softplus_fast(s1[6]), softplus_fast(s1[7]));
        }
    }
}

// ================= kernel B: mixing GEMM + epilogue (persistent) ============
__global__ void __launch_bounds__(THREADS, 2)
mixing_kernel(const float* __restrict__ z,
              const float* __restrict__ gb,
              float* __restrict__ out)
{
    extern __shared__ char smem[];
    float* scs = (float*)(smem + B_SC_B);
    float* gts = (float*)(smem + B_G_B);

    const int tid = threadIdx.x;
    const int wid = tid >> 5;
    const int lid = tid & 31;
    const uint32_t smb = s2u(smem);

    // ---- one-time staging: mixing weight fragments + gates ----
    {
        const float4* s = (const float4*)gWpk;
        float4* d4 = (float4*)(smem + B_WH_B);
        #pragma unroll
        for (int e = 0; e < 8; ++e) d4[e * 256 + tid] = s[e * 256 + tid];
    }
    if (tid < 8) gts[tid] = 1.0f / (1.0f + __expf(-gb[tid]));
    __syncthreads();

    const int mw = wid & 3;
    const int nh = wid >> 2;
    const int qt = lid >> 2;
    const int qc = lid & 3;
    const int lm_row = ((lid >> 3) & 1) * 8 + (lid & 7);
    const int lm_col = (lid >> 4) * 16;
    const char* wbase = smem + B_WH_B + nh * 16384;

    for (int t = 0; t < TILES; ++t) {
        const int blk = blockIdx.x * TILES + t;
        const int row0 = blk * 128;

        // ---- per-tile staging: scales + z bf16 ----
        ((float4*)scs)[tid] = ((const float4*)gScales)[blk * 256 + tid];
        {
            const float4* zg = (const float4*)(z + (size_t)row0 * 128);
            #pragma unroll
            for (int e = 0; e < 16; ++e) {
                int idx = e * 256 + tid;
                int row = idx >> 5;
                int c4  = idx & 31;
                float4 v = zg[idx];
                __nv_bfloat162 p0 = __floats2bfloat162_rn(v.x, v.y);
                __nv_bfloat162 p1 = __floats2bfloat162_rn(v.z, v.w);
                uint2 pr = make_uint2(*(uint32_t*)&p0, *(uint32_t*)&p1);
                *(uint2*)(smem + B_ZH_B + row * 272 + c4 * 8) = pr;
            }
        }
        __syncthreads();

        float4 acc[8], acc2[8];
        #pragma unroll
        for (int nt = 0; nt < 8; ++nt) {
            acc[nt]  = make_float4(0.f, 0.f, 0.f, 0.f);
            acc2[nt] = make_float4(0.f, 0.f, 0.f, 0.f);
        }

        const uint32_t abase = smb + B_ZH_B + (mw * 32 + lm_row) * 272 + lm_col;
        #pragma unroll
        for (int ks = 0; ks < 8; ++ks) {
            uint32_t a0, a1, a2, a3, c0, c1, c2, c3;
            ldsm4(a0, a1, a2, a3, abase + ks * 32);
            ldsm4(c0, c1, c2, c3, abase + 16 * 272 + ks * 32);
            const char* wp = wbase + ks * 2048 + lid * 16;
            uint4 l0 = *(const uint4*)(wp);
            uint4 l1 = *(const uint4*)(wp + 512);
            uint4 l2 = *(const uint4*)(wp + 1024);
            uint4 l3 = *(const uint4*)(wp + 1536);
            mma16bf(acc[0], a0, a1, a2, a3, l0.x, l0.y);
            mma16bf(acc[1], a0, a1, a2, a3, l0.z, l0.w);
            mma16bf(acc[2], a0, a1, a2, a3, l1.x, l1.y);
            mma16bf(acc[3], a0, a1, a2, a3, l1.z, l1.w);
            mma16bf(acc[4], a0, a1, a2, a3, l2.x, l2.y);
            mma16bf(acc[5], a0, a1, a2, a3, l2.z, l2.w);
            mma16bf(acc[6], a0, a1, a2, a3, l3.x, l3.y);
            mma16bf(acc[7], a0, a1, a2, a3, l3.z, l3.w);
            mma16bf(acc2[0], c0, c1, c2, c3, l0.x, l0.y);
            mma16bf(acc2[1], c0, c1, c2, c3, l0.z, l0.w);
            mma16bf(acc2[2], c0, c1, c2, c3, l1.x, l1.y);
            mma16bf(acc2[3], c0, c1, c2, c3, l1.z, l1.w);
            mma16bf(acc2[4], c0, c1, c2, c3, l2.x, l2.y);
            mma16bf(acc2[5], c0, c1, c2, c3, l2.z, l2.w);
            mma16bf(acc2[6], c0, c1, c2, c3, l3.x, l3.y);
            mma16bf(acc2[7], c0, c1, c2, c3, l3.z, l3.w);
        }

        // ---- epilogue: z fp32 re-read from global (L2-resident tile) ----
        #pragma unroll
        for (int nt = 0; nt < 8; ++nt) {
            const int bundle = nh * 4 + (nt >> 1);
            const float g = gts[bundle];
            const int x0 = nh * 64 + nt * 8 + 2 * qc;
            #pragma unroll
            for (int mt = 0; mt < 2; ++mt) {
                float4 a = (mt == 0) ? acc[nt] : acc2[nt];
                #pragma unroll
                for (int rh = 0; rh < 2; ++rh) {
                    const int r = mw * 32 + mt * 16 + rh * 8 + qt;
                    const float s1 = 1.0f + scs[r * 8 + bundle];
                    float2 zv = *(const float2*)(z + (size_t)(row0 + r) * 128 + x0);
                    float m0 = (rh == 0) ? a.x : a.z;
                    float m1 = (rh == 0) ? a.y : a.w;
                    float2 o = make_float2(zv.x * s1 + g * m0, zv.y * s1 + g * m1);
                    *(float2*)(out + (size_t)(row0 + r) * 128 + x0) = o;
                }
            }
        }
        __syncthreads();     // tile fence before ZH/scs reuse
    }
}

extern "C" void kernel_launch(void* const* d_in, const int* in_sizes, int n_in,
                              void* d_out, int out_size)
{
    const float* z    = (const float*)d_in[0];
    const float* w1   = (const float*)d_in[1];
    const float* b1   = (const float*)d_in[2];
    const float* w2   = (const float*)d_in[3];
    const float* b2   = (const float*)d_in[4];
    const float* w3   = (const float*)d_in[5];
    const float* mixw = (const float*)d_in[6];
    const float* gb   = (const float*)d_in[7];
    float* out = (float*)d_out;

    int Btot = in_sizes[0] / 128;                 // 524288 rows
    int nblocks = Btot / (128 * TILES);           // 1024

    prep_kernel<<<64, 256>>>(mixw);
    prep2_kernel<<<16, 256>>>(w2);
    prep3_kernel<<<2, 256>>>(w1);

    static bool attr_set = false;
    if (!attr_set) {
        cudaFuncSetAttribute(mixing_kernel,
                             cudaFuncAttributeMaxDynamicSharedMemorySize, B_SMEM);
        attr_set = true;
    }
    scales_kernel<<<nblocks, THREADS, A_SMEM>>>(z, b1, b2, w3);
    mixing_kernel<<<nblocks, THREADS, B_SMEM>>>(z, gb, out);
}